// round 8
// baseline (speedup 1.0000x reference)
#include <cuda_runtime.h>
#include <cstdint>

#define B_TOTAL 65536
#define TLEN 200
#define NSTEP 101
#define TPB 128          // 4 warps = 2 warp-pairs; each pair: 64 samples
#define HSTRIDE 53       // b64 per lane row in h slab (>= 52 to hold padded unit 51; conflict-free)
#define KSTRIDE 7        // b64 per lane row in k slab

typedef unsigned long long u64;

__device__ float g_y0[B_TOTAL * 6];

// ---------------- f32x2 helpers ----------------
__device__ __forceinline__ u64 pack_dup(float v) {
    u64 r; asm("mov.b64 %0, {%1, %2};" : "=l"(r) : "f"(v), "f"(v)); return r;
}
__device__ __forceinline__ u64 pack2f(float a, float b) {
    u64 r; asm("mov.b64 %0, {%1, %2};" : "=l"(r) : "f"(a), "f"(b)); return r;
}
__device__ __forceinline__ void unpack2(u64 v, float& lo, float& hi) {
    asm("mov.b64 {%0, %1}, %2;" : "=f"(lo), "=f"(hi) : "l"(v));
}
__device__ __forceinline__ u64 ffma2(u64 a, u64 b, u64 c) {
    u64 d; asm("fma.rn.f32x2 %0, %1, %2, %3;" : "=l"(d) : "l"(a), "l"(b), "l"(c)); return d;
}
__device__ __forceinline__ unsigned smem_addr(const void* p) {
    return (unsigned)__cvta_generic_to_shared(p);
}
__device__ __forceinline__ void lds2(unsigned a, u64& x, u64& y) {
    asm("ld.shared.v2.u64 {%0, %1}, [%2];" : "=l"(x), "=l"(y) : "r"(a));
}
__device__ __forceinline__ u64 lds1(unsigned a) {
    u64 x; asm("ld.shared.u64 %0, [%1];" : "=l"(x) : "r"(a)); return x;
}
__device__ __forceinline__ void sts1(unsigned a, u64 v) {
    asm volatile("st.shared.u64 [%0], %1;" :: "r"(a), "l"(v));
}
__device__ __forceinline__ float ldsf(unsigned a) {
    float x; asm("ld.shared.f32 %0, [%1];" : "=f"(x) : "r"(a)); return x;
}
__device__ __forceinline__ void pair_bar(int id) {
    asm volatile("bar.sync %0, 64;" :: "r"(id) : "memory");
}

// float offsets inside dynamic smem (all 16B-aligned)
#define OFF_W1   0
#define OFF_W2   (OFF_W1 + 6 * 56)          // 336
#define OFF_W3   (OFF_W2 + 50 * 56)         // 3136
#define OFF_B1   (OFF_W3 + 52 * 8)          // 3552
#define OFF_B2   (OFF_B1 + 56)              // 3608
#define OFF_TS   (OFF_B2 + 56)              // 3664
#define OFF_H    (OFF_TS + 104)             // 3768
#define OFF_K    (OFF_H + 2 * 32 * HSTRIDE * 2)          // 3768 + 6784 = 10552
#define SMEM_FLOATS (OFF_K + 2 * 2 * 32 * KSTRIDE * 2)   // 10552 + 1792 = 12344
#define SMEM_BYTES (SMEM_FLOATS * 4)                     // 49376

// ---------------- Phase A: y0 = mean over T (warp per sample) ----------------
__global__ void mean_kernel(const float* __restrict__ x0) {
    const unsigned w = (blockIdx.x * blockDim.x + threadIdx.x) >> 5;
    const int lane = threadIdx.x & 31;
    if (w >= B_TOTAL) return;
    const float2* p = reinterpret_cast<const float2*>(x0) + (size_t)w * 600u;
    float sx = 0.0f, sy = 0.0f;
    if (lane < 30) {
        #pragma unroll
        for (int kk = 0; kk < 20; kk++) {
            float2 v = __ldg(p + lane + 30 * kk);
            sx += v.x;
            sy += v.y;
        }
    }
    const int c = lane % 3;
    float v0 = (c == 0) ? sx : 0.0f, v1 = (c == 0) ? sy : 0.0f;
    float v2 = (c == 1) ? sx : 0.0f, v3 = (c == 1) ? sy : 0.0f;
    float v4 = (c == 2) ? sx : 0.0f, v5 = (c == 2) ? sy : 0.0f;
    #pragma unroll
    for (int o = 16; o; o >>= 1) {
        v0 += __shfl_xor_sync(0xffffffffu, v0, o);
        v1 += __shfl_xor_sync(0xffffffffu, v1, o);
        v2 += __shfl_xor_sync(0xffffffffu, v2, o);
        v3 += __shfl_xor_sync(0xffffffffu, v3, o);
        v4 += __shfl_xor_sync(0xffffffffu, v4, o);
        v5 += __shfl_xor_sync(0xffffffffu, v5, o);
    }
    if (lane == 0) {
        const float inv = 1.0f / (float)TLEN;
        float* o = g_y0 + (size_t)w * 6u;
        o[0] = v0 * inv; o[1] = v1 * inv; o[2] = v2 * inv;
        o[3] = v3 * inv; o[4] = v4 * inv; o[5] = v5 * inv;
    }
}

// ---------------- Phase B: RK4. Warp pair shares 64 samples; each warp owns
// half the hidden units for BOTH of its lane's 2 samples (A = base+lane, B = +32).
__global__ void __launch_bounds__(TPB, 4) ode_kernel(
    const float* __restrict__ t_span,
    const float* __restrict__ W1, const float* __restrict__ b1,
    const float* __restrict__ W2, const float* __restrict__ b2,
    const float* __restrict__ W3, const float* __restrict__ b3,
    float* __restrict__ out) {
    extern __shared__ __align__(16) float sm[];

    const int t = threadIdx.x;
    // zero pads + virtual rows
    for (int i = t; i < OFF_B2 + 56; i += TPB) sm[i] = 0.0f;
    __syncthreads();
    for (int i = t; i < 6 * 50; i += TPB) {
        int d = i / 50, c = i % 50;
        sm[OFF_W1 + d * 56 + (c / 26) * 28 + (c % 26)] = W1[i];
    }
    for (int i = t; i < 50 * 50; i += TPB) {
        int r = i / 50, c = i % 50;
        sm[OFF_W2 + r * 56 + (c / 26) * 28 + (c % 26)] = W2[i];
    }
    for (int i = t; i < 50 * 6; i += TPB) {
        int r = i / 6, c = i % 6;
        sm[OFF_W3 + r * 8 + c] = W3[i];
    }
    if (t < 50) {
        sm[OFF_B1 + (t / 26) * 28 + (t % 26)] = b1[t];
        sm[OFF_B2 + (t / 26) * 28 + (t % 26)] = b2[t];
    }
    for (int i = t; i < NSTEP + 1; i += TPB) sm[OFF_TS + i] = t_span[i];
    __syncthreads();

    const int lane = t & 31;
    const int warp = t >> 5;
    const int pair = warp >> 1;      // 0 or 1
    const int half = warp & 1;       // 0 or 1 (warp-uniform)
    const int barid = pair + 1;
    const int gidA = blockIdx.x * 128 + pair * 64 + lane;   // sample A
    const int gidB = gidA + 32;                              // sample B

    const unsigned base = smem_addr(sm);
    const unsigned colOff = (unsigned)half * 112u;           // 28 floats
    const unsigned aW1 = base + OFF_W1 * 4u + colOff;
    const unsigned aW2 = base + OFF_W2 * 4u + colOff;
    const unsigned aB1 = base + OFF_B1 * 4u + colOff;
    const unsigned aB2 = base + OFF_B2 * 4u + colOff;
    const unsigned aW3 = base + OFF_W3 * 4u + (unsigned)half * 832u;  // 26 rows * 32B
    const unsigned aTs = base + OFF_TS * 4u;
    // h slab: row per (pair, lane), HSTRIDE b64; entry i = unit i as (s0,s1) b64
    const unsigned aHrow = base + OFF_H * 4u
                         + ((unsigned)(pair * 32 + lane) * HSTRIDE) * 8u;
    const unsigned aHw = aHrow + (unsigned)(half * 26) * 8u;
    // k slab: row per (pair, half, lane), KSTRIDE b64
    const unsigned aKw = base + OFF_K * 4u
                       + ((unsigned)((pair * 2 + half) * 32 + lane) * KSTRIDE) * 8u;
    const unsigned aKr = base + OFF_K * 4u
                       + ((unsigned)((pair * 2 + (half ^ 1)) * 32 + lane) * KSTRIDE) * 8u;

    float bb3[6];
    #pragma unroll
    for (int d = 0; d < 6; d++) bb3[d] = __ldg(b3 + d);

    float yA[6], yB[6];
    #pragma unroll
    for (int d = 0; d < 6; d++) {
        yA[d] = g_y0[gidA * 6 + d];
        yB[d] = g_y0[gidB * 6 + d];
    }

    float ytA[6], ytB[6], accA[6], accB[6];

    #pragma unroll 1
    for (int stp = 0; stp < NSTEP; stp++) {
        const float dt = ldsf(aTs + (unsigned)(4 * stp + 4)) - ldsf(aTs + (unsigned)(4 * stp));
        #pragma unroll
        for (int d = 0; d < 6; d++) { ytA[d] = yA[d]; ytB[d] = yB[d]; }
        #pragma unroll 1
        for (int st = 0; st < 4; st++) {
            // ---- layer 1: own 26-unit half of h1, both samples ----
            u64 hA[13], hB[13];
            lds2(aB1,      hA[0],  hA[1]);
            lds2(aB1 + 16, hA[2],  hA[3]);
            lds2(aB1 + 32, hA[4],  hA[5]);
            lds2(aB1 + 48, hA[6],  hA[7]);
            lds2(aB1 + 64, hA[8],  hA[9]);
            lds2(aB1 + 80, hA[10], hA[11]);
            hA[12] = lds1(aB1 + 96);
            #pragma unroll
            for (int p = 0; p < 13; p++) hB[p] = hA[p];
            #pragma unroll
            for (int d = 0; d < 6; d++) {
                u64 mA = pack_dup(ytA[d]);
                u64 mB = pack_dup(ytB[d]);
                unsigned r = aW1 + d * 224;
                #pragma unroll
                for (int c = 0; c < 6; c++) {
                    u64 w0, w1;
                    lds2(r + 16 * c, w0, w1);
                    hA[2 * c]     = ffma2(mA, w0, hA[2 * c]);
                    hA[2 * c + 1] = ffma2(mA, w1, hA[2 * c + 1]);
                    hB[2 * c]     = ffma2(mB, w0, hB[2 * c]);
                    hB[2 * c + 1] = ffma2(mB, w1, hB[2 * c + 1]);
                }
                u64 wl = lds1(r + 96);
                hA[12] = ffma2(mA, wl, hA[12]);
                hB[12] = ffma2(mB, wl, hB[12]);
            }
            // transpose to (s0,s1) per unit, ReLU, park in smem
            #pragma unroll
            for (int p = 0; p < 13; p++) {
                float a0, a1, b0, b1;
                unpack2(hA[p], a0, a1);
                unpack2(hB[p], b0, b1);
                sts1(aHw + (unsigned)(16 * p),
                     pack2f(fmaxf(a0, 0.0f), fmaxf(b0, 0.0f)));
                sts1(aHw + (unsigned)(16 * p + 8),
                     pack2f(fmaxf(a1, 0.0f), fmaxf(b1, 0.0f)));
            }
            pair_bar(barid);   // both halves of h1 visible

            // ---- layer 2: own half of h2, all 50 inputs, both samples ----
            u64 gA[13], gB[13];
            lds2(aB2,      gA[0],  gA[1]);
            lds2(aB2 + 16, gA[2],  gA[3]);
            lds2(aB2 + 32, gA[4],  gA[5]);
            lds2(aB2 + 48, gA[6],  gA[7]);
            lds2(aB2 + 64, gA[8],  gA[9]);
            lds2(aB2 + 80, gA[10], gA[11]);
            gA[12] = lds1(aB2 + 96);
            #pragma unroll
            for (int p = 0; p < 13; p++) gB[p] = gA[p];
            #pragma unroll 1
            for (int i = 0; i < 50; i++) {
                float ma, mb;
                unpack2(lds1(aHrow + (unsigned)(8 * i)), ma, mb);
                u64 mA = pack_dup(ma);
                u64 mB = pack_dup(mb);
                unsigned r = aW2 + i * 224;
                #pragma unroll
                for (int c = 0; c < 6; c++) {
                    u64 w0, w1;
                    lds2(r + 16 * c, w0, w1);
                    gA[2 * c]     = ffma2(mA, w0, gA[2 * c]);
                    gA[2 * c + 1] = ffma2(mA, w1, gA[2 * c + 1]);
                    gB[2 * c]     = ffma2(mB, w0, gB[2 * c]);
                    gB[2 * c + 1] = ffma2(mB, w1, gB[2 * c + 1]);
                }
                u64 wl = lds1(r + 96);
                gA[12] = ffma2(mA, wl, gA[12]);
                gB[12] = ffma2(mB, wl, gB[12]);
            }

            // ---- layer 3: partial k over own 26 h2 units, both samples ----
            u64 oA0 = 0ull, oA1 = 0ull, oA2 = 0ull;
            u64 oB0 = 0ull, oB1 = 0ull, oB2 = 0ull;
            #pragma unroll 1
            for (int p = 0; p < 13; p++) {
                float ax, az, bx, bz;
                unpack2(gA[p], ax, az);
                unpack2(gB[p], bx, bz);
                u64 mA0 = pack_dup(fmaxf(ax, 0.0f));
                u64 mA1 = pack_dup(fmaxf(az, 0.0f));
                u64 mB0 = pack_dup(fmaxf(bx, 0.0f));
                u64 mB1 = pack_dup(fmaxf(bz, 0.0f));
                unsigned r = aW3 + (unsigned)(2 * p) * 32u;
                u64 w0, w1, wl;
                lds2(r, w0, w1);
                wl = lds1(r + 16);
                oA0 = ffma2(mA0, w0, oA0); oA1 = ffma2(mA0, w1, oA1); oA2 = ffma2(mA0, wl, oA2);
                oB0 = ffma2(mB0, w0, oB0); oB1 = ffma2(mB0, w1, oB1); oB2 = ffma2(mB0, wl, oB2);
                lds2(r + 32, w0, w1);
                wl = lds1(r + 48);
                oA0 = ffma2(mA1, w0, oA0); oA1 = ffma2(mA1, w1, oA1); oA2 = ffma2(mA1, wl, oA2);
                oB0 = ffma2(mB1, w0, oB0); oB1 = ffma2(mB1, w1, oB1); oB2 = ffma2(mB1, wl, oB2);
            }
            float kpA[6], kpB[6];
            unpack2(oA0, kpA[0], kpA[1]); unpack2(oA1, kpA[2], kpA[3]); unpack2(oA2, kpA[4], kpA[5]);
            unpack2(oB0, kpB[0], kpB[1]); unpack2(oB1, kpB[2], kpB[3]); unpack2(oB2, kpB[4], kpB[5]);
            #pragma unroll
            for (int d = 0; d < 6; d++) sts1(aKw + (unsigned)(8 * d), pack2f(kpA[d], kpB[d]));
            pair_bar(barid);   // partner's partial k visible (also orders next h store)
            float kA[6], kB[6];
            #pragma unroll
            for (int d = 0; d < 6; d++) {
                float pa, pb;
                unpack2(lds1(aKr + (unsigned)(8 * d)), pa, pb);
                kA[d] = (kpA[d] + pa) + bb3[d];   // commutative: identical in both warps
                kB[d] = (kpB[d] + pb) + bb3[d];
            }

            if (st == 0) {
                #pragma unroll
                for (int d = 0; d < 6; d++) {
                    accA[d] = kA[d]; ytA[d] = fmaf(0.5f * dt, kA[d], yA[d]);
                    accB[d] = kB[d]; ytB[d] = fmaf(0.5f * dt, kB[d], yB[d]);
                }
            } else if (st == 1) {
                #pragma unroll
                for (int d = 0; d < 6; d++) {
                    accA[d] += 2.0f * kA[d]; ytA[d] = fmaf(0.5f * dt, kA[d], yA[d]);
                    accB[d] += 2.0f * kB[d]; ytB[d] = fmaf(0.5f * dt, kB[d], yB[d]);
                }
            } else if (st == 2) {
                #pragma unroll
                for (int d = 0; d < 6; d++) {
                    accA[d] += 2.0f * kA[d]; ytA[d] = fmaf(dt, kA[d], yA[d]);
                    accB[d] += 2.0f * kB[d]; ytB[d] = fmaf(dt, kB[d], yB[d]);
                }
            } else {
                #pragma unroll
                for (int d = 0; d < 6; d++) {
                    yA[d] = fmaf(dt * (1.0f / 6.0f), accA[d] + kA[d], yA[d]);
                    yB[d] = fmaf(dt * (1.0f / 6.0f), accB[d] + kB[d], yB[d]);
                }
            }
        }
    }

    if (half == 0) {
        #pragma unroll
        for (int d = 0; d < 6; d++) {
            out[gidA * 6 + d] = yA[d];
            out[gidB * 6 + d] = yB[d];
        }
    }
}

extern "C" void kernel_launch(void* const* d_in, const int* in_sizes, int n_in,
                              void* d_out, int out_size) {
    const float* x0 = (const float*)d_in[0];
    const float* ts = (const float*)d_in[1];
    const float* W1 = (const float*)d_in[2];
    const float* b1 = (const float*)d_in[3];
    const float* W2 = (const float*)d_in[4];
    const float* b2 = (const float*)d_in[5];
    const float* W3 = (const float*)d_in[6];
    const float* b3 = (const float*)d_in[7];
    float* out = (float*)d_out;

    static bool attr_set = false;
    if (!attr_set) {
        cudaFuncSetAttribute(ode_kernel,
                             cudaFuncAttributeMaxDynamicSharedMemorySize, SMEM_BYTES);
        attr_set = true;
    }

    mean_kernel<<<8192, 256>>>(x0);
    // 128 samples per block (2 pairs x 64), 2 samples per thread
    ode_kernel<<<B_TOTAL / 128, TPB, SMEM_BYTES>>>(ts, W1, b1, W2, b2, W3, b3, out);
}

// round 10
// speedup vs baseline: 1.6030x; 1.6030x over previous
#include <cuda_runtime.h>
#include <cstdint>

#define B_TOTAL 65536
#define TLEN 200
#define NSTEP 101
#define TPB 128          // one warp-quad per block; 64 samples per block
#define HSTRIDE 53       // b64 per lane row in h slab (holds unit indices 0..51; conflict-free)

typedef unsigned long long u64;

__device__ float g_y0[B_TOTAL * 6];

// ---------------- f32x2 helpers ----------------
__device__ __forceinline__ u64 pack_dup(float v) {
    u64 r; asm("mov.b64 %0, {%1, %2};" : "=l"(r) : "f"(v), "f"(v)); return r;
}
__device__ __forceinline__ u64 pack2f(float a, float b) {
    u64 r; asm("mov.b64 %0, {%1, %2};" : "=l"(r) : "f"(a), "f"(b)); return r;
}
__device__ __forceinline__ void unpack2(u64 v, float& lo, float& hi) {
    asm("mov.b64 {%0, %1}, %2;" : "=f"(lo), "=f"(hi) : "l"(v));
}
__device__ __forceinline__ u64 ffma2(u64 a, u64 b, u64 c) {
    u64 d; asm("fma.rn.f32x2 %0, %1, %2, %3;" : "=l"(d) : "l"(a), "l"(b), "l"(c)); return d;
}
__device__ __forceinline__ unsigned smem_addr(const void* p) {
    return (unsigned)__cvta_generic_to_shared(p);
}
__device__ __forceinline__ void lds2(unsigned a, u64& x, u64& y) {
    asm("ld.shared.v2.u64 {%0, %1}, [%2];" : "=l"(x), "=l"(y) : "r"(a));
}
__device__ __forceinline__ u64 lds1(unsigned a) {
    u64 x; asm("ld.shared.u64 %0, [%1];" : "=l"(x) : "r"(a)); return x;
}
__device__ __forceinline__ void sts1(unsigned a, u64 v) {
    asm volatile("st.shared.u64 [%0], %1;" :: "r"(a), "l"(v));
}
__device__ __forceinline__ float ldsf(unsigned a) {
    float x; asm("ld.shared.f32 %0, [%1];" : "=f"(x) : "r"(a)); return x;
}

// ---------------- Phase A: y0 = mean over T (warp per sample) ----------------
__global__ void mean_kernel(const float* __restrict__ x0) {
    const unsigned w = (blockIdx.x * blockDim.x + threadIdx.x) >> 5;
    const int lane = threadIdx.x & 31;
    if (w >= B_TOTAL) return;
    const float2* p = reinterpret_cast<const float2*>(x0) + (size_t)w * 600u;
    float sx = 0.0f, sy = 0.0f;
    if (lane < 30) {
        #pragma unroll
        for (int kk = 0; kk < 20; kk++) {
            float2 v = __ldg(p + lane + 30 * kk);
            sx += v.x;
            sy += v.y;
        }
    }
    const int c = lane % 3;
    float v0 = (c == 0) ? sx : 0.0f, v1 = (c == 0) ? sy : 0.0f;
    float v2 = (c == 1) ? sx : 0.0f, v3 = (c == 1) ? sy : 0.0f;
    float v4 = (c == 2) ? sx : 0.0f, v5 = (c == 2) ? sy : 0.0f;
    #pragma unroll
    for (int o = 16; o; o >>= 1) {
        v0 += __shfl_xor_sync(0xffffffffu, v0, o);
        v1 += __shfl_xor_sync(0xffffffffu, v1, o);
        v2 += __shfl_xor_sync(0xffffffffu, v2, o);
        v3 += __shfl_xor_sync(0xffffffffu, v3, o);
        v4 += __shfl_xor_sync(0xffffffffu, v4, o);
        v5 += __shfl_xor_sync(0xffffffffu, v5, o);
    }
    if (lane == 0) {
        const float inv = 1.0f / (float)TLEN;
        float* o = g_y0 + (size_t)w * 6u;
        o[0] = v0 * inv; o[1] = v1 * inv; o[2] = v2 * inv;
        o[3] = v3 * inv; o[4] = v4 * inv; o[5] = v5 * inv;
    }
}

// Column mapping: hidden unit u -> padded col (u/13)*16 + (u%13) in 64-float rows.
// Warp w owns units [13w, 13w+13) = padded cols [16w, 16w+16); pad cols are zero.
__global__ void __launch_bounds__(TPB, 4) ode_kernel(
    const float* __restrict__ t_span,
    const float* __restrict__ W1, const float* __restrict__ b1,
    const float* __restrict__ W2, const float* __restrict__ b2,
    const float* __restrict__ W3, const float* __restrict__ b3,
    float* __restrict__ out) {
    __shared__ __align__(16) float sW1[6 * 64];
    __shared__ __align__(16) float sW2[50 * 64];
    __shared__ __align__(16) float sW3q[4 * 16 * 8];  // [w][j][c], row 13w+j (zero if pad)
    __shared__ __align__(16) float sB1[64];
    __shared__ __align__(16) float sB2[64];
    __shared__ __align__(16) float sTs[NSTEP + 1];
    __shared__ __align__(16) u64  sH[32 * HSTRIDE];   // [lane][unit 0..51], stride 53 b64
    __shared__ __align__(16) u64  sK[4 * 32 * 7];     // [warp][lane][d]

    const int t = threadIdx.x;
    // zero padded weight/bias regions
    for (int i = t; i < 6 * 64; i += TPB) sW1[i] = 0.0f;
    for (int i = t; i < 50 * 64; i += TPB) sW2[i] = 0.0f;
    if (t < 64) { sB1[t] = 0.0f; sB2[t] = 0.0f; }
    __syncthreads();
    // scatter real weights
    for (int i = t; i < 6 * 50; i += TPB) {
        int d = i / 50, u = i % 50;
        sW1[d * 64 + (u / 13) * 16 + (u % 13)] = W1[i];
    }
    for (int i = t; i < 50 * 50; i += TPB) {
        int r = i / 50, u = i % 50;
        sW2[r * 64 + (u / 13) * 16 + (u % 13)] = W2[i];
    }
    for (int i = t; i < 4 * 16 * 8; i += TPB) {
        int q = i / 128, j = (i / 8) % 16, c = i % 8;
        int row = 13 * q + j;
        sW3q[i] = (j < 13 && row < 50 && c < 6) ? W3[row * 6 + c] : 0.0f;
    }
    if (t < 50) {
        sB1[(t / 13) * 16 + (t % 13)] = b1[t];
        sB2[(t / 13) * 16 + (t % 13)] = b2[t];
    }
    for (int i = t; i < NSTEP + 1; i += TPB) sTs[i] = t_span[i];
    __syncthreads();

    const int lane = t & 31;
    const int w = t >> 5;                        // quarter id, warp-uniform
    const int gidA = blockIdx.x * 64 + lane;
    const int gidB = gidA + 32;

    const unsigned colOff = (unsigned)w * 64u;   // 16 floats
    const unsigned aW1 = smem_addr(sW1) + colOff;
    const unsigned aW2 = smem_addr(sW2) + colOff;
    const unsigned aB1 = smem_addr(sB1) + colOff;
    const unsigned aB2 = smem_addr(sB2) + colOff;
    const unsigned aW3 = smem_addr(sW3q) + (unsigned)w * 512u;  // 16 rows * 32B
    const unsigned aTs = smem_addr(sTs);
    const unsigned aHrow = smem_addr(sH) + (unsigned)lane * (HSTRIDE * 8u);  // 424B rows
    const unsigned aHw = aHrow + (unsigned)w * 104u;                // unit 13w
    const unsigned aK0 = smem_addr(sK) + (unsigned)lane * 56u;      // 7 b64
    const unsigned aKw = aK0 + (unsigned)w * 1792u;                 // 32*56

    float bb3[6];
    #pragma unroll
    for (int d = 0; d < 6; d++) bb3[d] = __ldg(b3 + d);

    float yA[6], yB[6];
    #pragma unroll
    for (int d = 0; d < 6; d++) {
        yA[d] = g_y0[gidA * 6 + d];
        yB[d] = g_y0[gidB * 6 + d];
    }

    float ytA[6], ytB[6], accA[6], accB[6];

    #pragma unroll 1
    for (int stp = 0; stp < NSTEP; stp++) {
        const float dt = ldsf(aTs + (unsigned)(4 * stp + 4)) - ldsf(aTs + (unsigned)(4 * stp));
        #pragma unroll
        for (int d = 0; d < 6; d++) { ytA[d] = yA[d]; ytB[d] = yB[d]; }
        #pragma unroll 1
        for (int st = 0; st < 4; st++) {
            // ---- layer 1: own 16-col (13 real) quarter of h1, both samples ----
            u64 hA[8], hB[8];
            lds2(aB1,      hA[0], hA[1]);
            lds2(aB1 + 16, hA[2], hA[3]);
            lds2(aB1 + 32, hA[4], hA[5]);
            lds2(aB1 + 48, hA[6], hA[7]);
            #pragma unroll
            for (int p = 0; p < 8; p++) hB[p] = hA[p];
            #pragma unroll
            for (int d = 0; d < 6; d++) {
                u64 mA = pack_dup(ytA[d]);
                u64 mB = pack_dup(ytB[d]);
                unsigned r = aW1 + d * 256;
                #pragma unroll
                for (int c = 0; c < 4; c++) {
                    u64 w0, w1;
                    lds2(r + 16 * c, w0, w1);
                    hA[2 * c]     = ffma2(mA, w0, hA[2 * c]);
                    hA[2 * c + 1] = ffma2(mA, w1, hA[2 * c + 1]);
                    hB[2 * c]     = ffma2(mB, w0, hB[2 * c]);
                    hB[2 * c + 1] = ffma2(mB, w1, hB[2 * c + 1]);
                }
            }
            // park ReLU(h1) for own 13 real units as (sA, sB) b64
            #pragma unroll
            for (int p = 0; p < 6; p++) {
                float a0, a1, b0, b1;
                unpack2(hA[p], a0, a1);
                unpack2(hB[p], b0, b1);
                sts1(aHw + (unsigned)(16 * p),
                     pack2f(fmaxf(a0, 0.0f), fmaxf(b0, 0.0f)));
                sts1(aHw + (unsigned)(16 * p + 8),
                     pack2f(fmaxf(a1, 0.0f), fmaxf(b1, 0.0f)));
            }
            {
                float a0, a1, b0, b1;
                unpack2(hA[6], a0, a1);
                unpack2(hB[6], b0, b1);
                sts1(aHw + 96u, pack2f(fmaxf(a0, 0.0f), fmaxf(b0, 0.0f)));
            }
            __syncthreads();   // all quarters of h1 visible

            // ---- layer 2: own quarter of h2, all 50 inputs, both samples ----
            u64 gA[8], gB[8];
            lds2(aB2,      gA[0], gA[1]);
            lds2(aB2 + 16, gA[2], gA[3]);
            lds2(aB2 + 32, gA[4], gA[5]);
            lds2(aB2 + 48, gA[6], gA[7]);
            #pragma unroll
            for (int p = 0; p < 8; p++) gB[p] = gA[p];
            #pragma unroll 2
            for (int i = 0; i < 50; i++) {
                float ma, mb;
                unpack2(lds1(aHrow + (unsigned)(8 * i)), ma, mb);
                u64 mA = pack_dup(ma);
                u64 mB = pack_dup(mb);
                unsigned r = aW2 + i * 256;
                #pragma unroll
                for (int c = 0; c < 4; c++) {
                    u64 w0, w1;
                    lds2(r + 16 * c, w0, w1);
                    gA[2 * c]     = ffma2(mA, w0, gA[2 * c]);
                    gA[2 * c + 1] = ffma2(mA, w1, gA[2 * c + 1]);
                    gB[2 * c]     = ffma2(mB, w0, gB[2 * c]);
                    gB[2 * c + 1] = ffma2(mB, w1, gB[2 * c + 1]);
                }
            }

            // ---- layer 3: partial k over own quarter (pads hit zero rows) ----
            u64 oA0 = 0ull, oA1 = 0ull, oA2 = 0ull;
            u64 oB0 = 0ull, oB1 = 0ull, oB2 = 0ull;
            #pragma unroll 2
            for (int p = 0; p < 8; p++) {
                float ax, az, bx, bz;
                unpack2(gA[p], ax, az);
                unpack2(gB[p], bx, bz);
                unsigned r = aW3 + (unsigned)(2 * p) * 32u;
                {
                    u64 mA = pack_dup(fmaxf(ax, 0.0f));
                    u64 mB = pack_dup(fmaxf(bx, 0.0f));
                    u64 w0, w1, wl;
                    lds2(r, w0, w1);
                    wl = lds1(r + 16);
                    oA0 = ffma2(mA, w0, oA0); oA1 = ffma2(mA, w1, oA1); oA2 = ffma2(mA, wl, oA2);
                    oB0 = ffma2(mB, w0, oB0); oB1 = ffma2(mB, w1, oB1); oB2 = ffma2(mB, wl, oB2);
                }
                {
                    u64 mA = pack_dup(fmaxf(az, 0.0f));
                    u64 mB = pack_dup(fmaxf(bz, 0.0f));
                    u64 w0, w1, wl;
                    lds2(r + 32, w0, w1);
                    wl = lds1(r + 48);
                    oA0 = ffma2(mA, w0, oA0); oA1 = ffma2(mA, w1, oA1); oA2 = ffma2(mA, wl, oA2);
                    oB0 = ffma2(mB, w0, oB0); oB1 = ffma2(mB, w1, oB1); oB2 = ffma2(mB, wl, oB2);
                }
            }
            float kpA[6], kpB[6];
            unpack2(oA0, kpA[0], kpA[1]); unpack2(oA1, kpA[2], kpA[3]); unpack2(oA2, kpA[4], kpA[5]);
            unpack2(oB0, kpB[0], kpB[1]); unpack2(oB1, kpB[2], kpB[3]); unpack2(oB2, kpB[4], kpB[5]);
            #pragma unroll
            for (int d = 0; d < 6; d++) sts1(aKw + (unsigned)(8 * d), pack2f(kpA[d], kpB[d]));
            __syncthreads();   // all partial k visible; also fences h-slab reuse

            float kA[6], kB[6];
            #pragma unroll
            for (int d = 0; d < 6; d++) {
                float a0, b0, a1, b1, a2, b2, a3, b3v;
                unpack2(lds1(aK0 +        (unsigned)(8 * d)), a0, b0);
                unpack2(lds1(aK0 + 1792u + (unsigned)(8 * d)), a1, b1);
                unpack2(lds1(aK0 + 3584u + (unsigned)(8 * d)), a2, b2);
                unpack2(lds1(aK0 + 5376u + (unsigned)(8 * d)), a3, b3v);
                // fixed order -> bit-identical across all 4 warps
                kA[d] = ((a0 + a1) + (a2 + a3)) + bb3[d];
                kB[d] = ((b0 + b1) + (b2 + b3v)) + bb3[d];
            }

            if (st == 0) {
                #pragma unroll
                for (int d = 0; d < 6; d++) {
                    accA[d] = kA[d]; ytA[d] = fmaf(0.5f * dt, kA[d], yA[d]);
                    accB[d] = kB[d]; ytB[d] = fmaf(0.5f * dt, kB[d], yB[d]);
                }
            } else if (st == 1) {
                #pragma unroll
                for (int d = 0; d < 6; d++) {
                    accA[d] += 2.0f * kA[d]; ytA[d] = fmaf(0.5f * dt, kA[d], yA[d]);
                    accB[d] += 2.0f * kB[d]; ytB[d] = fmaf(0.5f * dt, kB[d], yB[d]);
                }
            } else if (st == 2) {
                #pragma unroll
                for (int d = 0; d < 6; d++) {
                    accA[d] += 2.0f * kA[d]; ytA[d] = fmaf(dt, kA[d], yA[d]);
                    accB[d] += 2.0f * kB[d]; ytB[d] = fmaf(dt, kB[d], yB[d]);
                }
            } else {
                #pragma unroll
                for (int d = 0; d < 6; d++) {
                    yA[d] = fmaf(dt * (1.0f / 6.0f), accA[d] + kA[d], yA[d]);
                    yB[d] = fmaf(dt * (1.0f / 6.0f), accB[d] + kB[d], yB[d]);
                }
            }
        }
    }

    if (w == 0) {
        #pragma unroll
        for (int d = 0; d < 6; d++) {
            out[gidA * 6 + d] = yA[d];
            out[gidB * 6 + d] = yB[d];
        }
    }
}

extern "C" void kernel_launch(void* const* d_in, const int* in_sizes, int n_in,
                              void* d_out, int out_size) {
    const float* x0 = (const float*)d_in[0];
    const float* ts = (const float*)d_in[1];
    const float* W1 = (const float*)d_in[2];
    const float* b1 = (const float*)d_in[3];
    const float* W2 = (const float*)d_in[4];
    const float* b2 = (const float*)d_in[5];
    const float* W3 = (const float*)d_in[6];
    const float* b3 = (const float*)d_in[7];
    float* out = (float*)d_out;

    mean_kernel<<<8192, 256>>>(x0);
    // 64 samples per block, 4 warps (one hidden-quarter each), 2 samples per thread
    ode_kernel<<<B_TOTAL / 64, TPB>>>(ts, W1, b1, W2, b2, W3, b3, out);
}